// round 7
// baseline (speedup 1.0000x reference)
#include <cuda_runtime.h>
#include <cstdint>

// VectorQuantizer R7: tf32 mma.sync with cn folded into the GEMM (score
// emitted directly), 16-row warps for 2x occupancy, gated chunk filter,
// exact fp32 recheck (byte-identical to the R2 passer), fused loss finale.

#define NUM_CODES 1024
#define DIM       64
#define HW        1024
#define N_VEC     32768
#define N_TOTAL   2097152
#define TPB       128
#define NBLOCKS   512          // 64 vectors per CTA
#define NCHUNK    16           // 16 chunks x 64 codes
#define KSTEP     9            // 72 augmented dims / 8
#define CHUNK_U32 (8 * KSTEP * 64)   // 4608
#define EPS2      1.5e-3f      // >= 2x worst-case tf32 score-error bound
#define MAXCAND   24
#define DPAD      68           // D/z row stride (f32), conflict-free

// dynamic smem layout (bytes)
#define OFF_B     0            // 4608 u32                = 18432
#define OFF_D     18432        // 4 warps x 16 x 68 f32   = 17408
#define OFF_CAND  35840        // 24 x 128 i32            = 12288
#define OFF_RED   48128        // 128 f32                 = 512
#define SMEM_TOTAL 48640

__device__ float        g_cnorm[NUM_CODES];
__device__ float        g_partial[NBLOCKS];
__device__ uint32_t     g_bfrag[NUM_CODES * 72];   // 1.15 MB, fragment-ordered
__device__ unsigned int g_done;                    // zero-init; reset each run

__device__ __forceinline__ uint32_t f2tf32(float f) {
    uint32_t u; asm("cvt.rna.tf32.f32 %0, %1;" : "=r"(u) : "f"(f)); return u;
}
__device__ __forceinline__ void mma_tf32(float* d, const uint32_t* a,
                                         uint32_t b0, uint32_t b1) {
    asm("mma.sync.aligned.m16n8k8.row.col.f32.tf32.tf32.f32 "
        "{%0,%1,%2,%3}, {%4,%5,%6,%7}, {%8,%9}, {%0,%1,%2,%3};"
        : "+f"(d[0]), "+f"(d[1]), "+f"(d[2]), "+f"(d[3])
        : "r"(a[0]), "r"(a[1]), "r"(a[2]), "r"(a[3]), "r"(b0), "r"(b1));
}

// exact fp32 score, byte-identical sequence to the round-2 passing kernel;
// z read strided from gmem (same bits; L1/L2-hot).
__device__ __forceinline__ float exact_score(const float* __restrict__ cb, int k,
                                             const float* __restrict__ zp,
                                             float zn, float cn) {
    const float4* row = (const float4*)(cb + (size_t)k * DIM);
    float d = 0.0f;
#pragma unroll
    for (int i = 0; i < 16; i++) {
        float4 a = row[i];
        d = fmaf(a.x, zp[(size_t)(4 * i + 0) * HW], d);
        d = fmaf(a.y, zp[(size_t)(4 * i + 1) * HW], d);
        d = fmaf(a.z, zp[(size_t)(4 * i + 2) * HW], d);
        d = fmaf(a.w, zp[(size_t)(4 * i + 3) * HW], d);
    }
    return __fadd_rn(__fsub_rn(zn, __fmul_rn(2.0f, d)), cn);
}

// ---------------------------------------------------------------------------
// Prep: per-code warp computes cn and writes the 72-dim augmented B' frags.
// Frag layout: o = ((t*8 + j)*9 + kk)*64 + dstlane*2 + h, where
// code = t*64 + j*8 + (dstlane>>2), dim = kk*8 + (dstlane&3) + h*4,
// value = dim<64 ? c[code][dim] : (dim==64 ? cn : 0).
// ---------------------------------------------------------------------------
__global__ void prep_kernel(const float* __restrict__ cb) {
    int k = (blockIdx.x * blockDim.x + threadIdx.x) >> 5;
    int l = threadIdx.x & 31;
    if (k >= NUM_CODES) return;
    float2 v = *(const float2*)(cb + (size_t)k * DIM + 2 * l);
    float cn = fmaf(v.x, v.x, v.y * v.y);
#pragma unroll
    for (int off = 16; off; off >>= 1)
        cn += __shfl_xor_sync(0xFFFFFFFFu, cn, off);
    if (l == 0) g_cnorm[k] = cn;

    int t = k >> 6, j = (k >> 3) & 7, gidk = k & 7;
    uint32_t* base = g_bfrag + (size_t)((t * 8 + j) * KSTEP) * 64;
    for (int i = l; i < 72; i += 32) {
        int kk = i >> 3, r = i & 7, sub = r >> 1, h = r & 1;
        int dim = kk * 8 + sub + h * 4;
        float val = (dim < 64) ? cb[(size_t)k * DIM + dim]
                               : (dim == 64 ? cn : 0.0f);
        base[kk * 64 + (gidk * 4 + sub) * 2 + h] = f2tf32(val);
    }
}

// ---------------------------------------------------------------------------
// Main: 64 vectors/CTA, warp = one m16 tile (16 vectors), 2 threads/row
// split the 64 codebook columns of each chunk.
// ---------------------------------------------------------------------------
__global__ void __launch_bounds__(TPB, 4)
vq_main_kernel(const float* __restrict__ z,
               const float* __restrict__ cb,
               float* __restrict__ out,
               float* __restrict__ loss_out) {
    extern __shared__ __align__(16) unsigned char smem[];
    uint32_t* s_b   = (uint32_t*)(smem + OFF_B);
    float*    s_d   = (float*)(smem + OFF_D);
    int*      s_cand= (int*)(smem + OFF_CAND);
    float*    s_red = (float*)(smem + OFF_RED);

    const int tid  = threadIdx.x;
    const int w    = tid >> 5, lane = tid & 31;
    const int gid  = lane >> 2, tig = lane & 3;
    const int row  = lane & 15;        // filter row (vector within warp)
    const int half = lane >> 4;        // column half (0: cols 0-31, 1: 32-63)
    const int n    = blockIdx.x * 64 + w * 16 + row;
    const int b    = n >> 10, hw = n & (HW - 1);
    const float* zp = z + (size_t)b * DIM * HW + hw;

    float* dw = s_d + w * 16 * DPAD;   // this warp's 16x68 tile

    // Stage z rows into the (currently unused) D region for the A-frag build.
    for (int i = 0; i < 32; i++) {
        int c = half * 32 + i;
        dw[row * DPAD + c] = zp[(size_t)c * HW];
    }
    __syncwarp();

    // Build augmented tf32 A fragments: A'[r][c] = c<64 ? -2z : (c==64?1:0).
    uint32_t afr[KSTEP][4];
#pragma unroll
    for (int kk = 0; kk < KSTEP; kk++)
#pragma unroll
        for (int r = 0; r < 4; r++) {
            int rr = gid + ((r & 1) << 3);
            int cc = kk * 8 + tig + ((r >> 1) << 2);
            float val = (cc < 64) ? (-2.0f * dw[rr * DPAD + cc])
                                  : (cc == 64 ? 1.0f : 0.0f);
            afr[kk][r] = f2tf32(val);
        }
    __syncwarp();

    // Stage B chunk 0 (4608 u32 = 1152 uint4, 9 per thread).
    {
        const uint4* src = (const uint4*)g_bfrag;
#pragma unroll
        for (int i = 0; i < 9; i++) ((uint4*)s_b)[i * TPB + tid] = src[i * TPB + tid];
    }
    __syncthreads();

    float runmin = 3.402823466e38f, thr = 3.402823466e38f;
    int cnt = 0;

#pragma unroll 1
    for (int t = 0; t < NCHUNK; t++) {
        // prefetch next chunk into regs (overlaps mma)
        uint4 pf[9];
        if (t + 1 < NCHUNK) {
            const uint4* src = (const uint4*)(g_bfrag + (size_t)(t + 1) * CHUNK_U32);
#pragma unroll
            for (int i = 0; i < 9; i++) pf[i] = src[i * TPB + tid];
        }

        // mma: scores for 16 rows x 64 codes, emitted directly (cn folded).
#pragma unroll
        for (int j = 0; j < 8; j++) {
            float d0[4] = {0.f, 0.f, 0.f, 0.f};
#pragma unroll
            for (int kk = 0; kk < KSTEP; kk++) {
                uint2 bb = *(const uint2*)&s_b[((j * KSTEP + kk) * 32 + lane) * 2];
                mma_tf32(d0, afr[kk], bb.x, bb.y);
            }
            *(float2*)&dw[gid * DPAD + j * 8 + tig * 2]       = make_float2(d0[0], d0[1]);
            *(float2*)&dw[(gid + 8) * DPAD + j * 8 + tig * 2] = make_float2(d0[2], d0[3]);
        }
        __syncwarp();

        // Gated filter: lane-parallel min tree, scan only if it can matter.
        const float* drow = dw + row * DPAD + half * 32;
        float4 mm = *(const float4*)drow;
#pragma unroll
        for (int g = 1; g < 8; g++) {
            float4 q = *(const float4*)&drow[g * 4];
            mm.x = fminf(mm.x, q.x); mm.y = fminf(mm.y, q.y);
            mm.z = fminf(mm.z, q.z); mm.w = fminf(mm.w, q.w);
        }
        float cmin = fminf(fminf(mm.x, mm.y), fminf(mm.z, mm.w));
        if (cmin < thr) {
            int kb = t * 64 + half * 32;
#pragma unroll 1
            for (int c = 0; c < 32; c++) {     // ascending k, R5 semantics
                float s = drow[c];
                if (s < thr) {
                    if (cnt < MAXCAND) s_cand[cnt * TPB + tid] = kb + c;
                    cnt++;
                    if (s < runmin) { runmin = s; thr = runmin + EPS2; }
                }
            }
        }
        __syncthreads();                        // all warps done with s_b
        if (t + 1 < NCHUNK) {
#pragma unroll
            for (int i = 0; i < 9; i++) ((uint4*)s_b)[i * TPB + tid] = pf[i];
            __syncthreads();                    // s_b chunk t+1 ready
        }
    }

    // zn in the reference's sequential order (same bits as R2 passer).
    float zn = 0.0f;
    for (int c = 0; c < DIM; c++) {
        float zv = zp[(size_t)c * HW];
        zn = fmaf(zv, zv, zn);
    }

    // Exact selection among own-half candidates (ascending k, strict <).
    float best = 3.402823466e38f;
    int bestk = 0x7FFFFFFF;
    if (cnt <= MAXCAND) {
        for (int jj = 0; jj < cnt; jj++) {
            int k = s_cand[jj * TPB + tid];
            float s = exact_score(cb, k, zp, zn, g_cnorm[k]);
            if (s < best) { best = s; bestk = k; }
        }
    } else {  // deterministic fallback (P ~ 0): exact scan of own half-columns
        for (int t = 0; t < NCHUNK; t++)
            for (int c = 0; c < 32; c++) {
                int k = t * 64 + half * 32 + c;
                float s = exact_score(cb, k, zp, zn, g_cnorm[k]);
                if (s < best) { best = s; bestk = k; }
            }
    }

    // Merge the two column-halves; exact ties -> smaller k (first index).
    {
        float ob = __shfl_xor_sync(0xFFFFFFFFu, best, 16);
        int   ok = __shfl_xor_sync(0xFFFFFFFFu, bestk, 16);
        if (ob < best || (ob == best && ok < bestk)) { best = ob; bestk = ok; }
    }

    // Gather + straight-through output + loss (R2-identical rounding),
    // each thread writing its own 32 dims.
    const float* crow = cb + (size_t)bestk * DIM;
    float* op = out + (size_t)b * DIM * HW + hw;
    float lsum = 0.0f;
    for (int i = 0; i < 32; i++) {
        int c = half * 32 + i;
        float q = crow[c];
        float zv = zp[(size_t)c * HW];
        float d = __fsub_rn(q, zv);
        lsum = fmaf(d, d, lsum);
        op[(size_t)c * HW] = __fadd_rn(zv, d);
    }

    // Deterministic block reduction of loss partials.
    __syncthreads();
    s_red[tid] = lsum;
    __syncthreads();
#pragma unroll
    for (int st = TPB / 2; st > 0; st >>= 1) {
        if (tid < st) s_red[tid] += s_red[tid + st];
        __syncthreads();
    }
    if (tid == 0) g_partial[blockIdx.x] = s_red[0];

    // Fused finale: last CTA reduces all partials in fixed order.
    if (loss_out) {
        __shared__ unsigned int s_rank;
        if (tid == 0) {
            __threadfence();
            s_rank = atomicAdd(&g_done, 1u);
        }
        __syncthreads();
        if (s_rank == NBLOCKS - 1) {
            __threadfence();
            float s = g_partial[tid];
            s = s + g_partial[tid + 128];
            s = s + g_partial[tid + 256];
            s = s + g_partial[tid + 384];
            s_red[tid] = s;
            __syncthreads();
#pragma unroll
            for (int st = 64; st > 0; st >>= 1) {
                if (tid < st) s_red[tid] += s_red[tid + st];
                __syncthreads();
            }
            if (tid == 0) {
                loss_out[0] = s_red[0] * (1.25f / (float)N_TOTAL);
                g_done = 0;   // reset for graph replay
            }
        }
    }
}

// ---------------------------------------------------------------------------
extern "C" void kernel_launch(void* const* d_in, const int* in_sizes, int n_in,
                              void* d_out, int out_size) {
    const float* z  = (const float*)d_in[0];
    const float* cb = (const float*)d_in[1];
    float* out = (float*)d_out;
    float* loss_out = (out_size > N_TOTAL) ? (out + (out_size - 1)) : nullptr;

    cudaFuncSetAttribute(vq_main_kernel,
                         cudaFuncAttributeMaxDynamicSharedMemorySize, SMEM_TOTAL);

    prep_kernel<<<NUM_CODES * 32 / 256, 256>>>(cb);
    vq_main_kernel<<<NBLOCKS, TPB, SMEM_TOTAL>>>(z, cb, out, loss_out);
}

// round 8
// speedup vs baseline: 2.3001x; 2.3001x over previous
#include <cuda_runtime.h>
#include <cuda_bf16.h>
#include <cstdint>

// VectorQuantizer R8: bf16 m16n8k16 mma filter with the ENTIRE fragment
// codebook resident in smem (no mainloop barriers), register-fragment
// filter with bitmask candidates, exact fp32 recheck (R2 byte-identical).

#define NUM_CODES 1024
#define DIM       64
#define HW        1024
#define N_VEC     32768
#define N_TOTAL   2097152
#define TPB       512          // 16 warps, 256 vectors per CTA
#define NBLOCKS   128          // one wave
#define NPASS     16           // 16 passes x 8 groups x 8 codes
#define GPP       8
#define EPS2      1.5e-3f      // >= 2x worst-case bf16 score-error bound
#define INF       3.402823466e38f

// smem layout (bytes)
#define OFF_CB    0            // 1024 codes x 4 ksteps x 32 x 8B = 131072
#define OFF_Z     131072       // 256 rows x 64 f32               = 65536
#define OFF_CN    196608       // 1024 f32                        = 4096
#define OFF_BEST  200704       // 256 i32                         = 1024
#define OFF_RED   201728       // 512 f32                         = 2048
#define SMEM_TOTAL 203776

__device__ float        g_cnorm[NUM_CODES];
__device__ float        g_partial[NBLOCKS];
__device__ uint2        g_bfrag[NUM_CODES * 16];   // 128 KB bf16 B fragments
__device__ unsigned int g_done;

__device__ __forceinline__ uint32_t pk_bf2(float lo, float hi) {
    uint32_t u;
    asm("cvt.rn.bf16x2.f32 %0, %1, %2;" : "=r"(u) : "f"(hi), "f"(lo));
    return u;
}
// m16n8k16 row.col bf16: A 4 regs, B 2 regs, D 4 f32 accumulate-in-place
__device__ __forceinline__ void mma_bf16(float* d, const uint32_t* a,
                                         uint32_t b0, uint32_t b1) {
    asm("mma.sync.aligned.m16n8k16.row.col.f32.bf16.bf16.f32 "
        "{%0,%1,%2,%3}, {%4,%5,%6,%7}, {%8,%9}, {%0,%1,%2,%3};"
        : "+f"(d[0]), "+f"(d[1]), "+f"(d[2]), "+f"(d[3])
        : "r"(a[0]), "r"(a[1]), "r"(a[2]), "r"(a[3]), "r"(b0), "r"(b1));
}

// exact fp32 score, byte-identical sequence to the round-2 passing kernel;
// z comes from the smem stage (same bits as the gmem values).
__device__ __forceinline__ float exact_score(const float* __restrict__ cb, int k,
                                             const float* zrow, float zn, float cn) {
    const float4* row = (const float4*)(cb + (size_t)k * DIM);
    float d = 0.0f;
#pragma unroll
    for (int i = 0; i < 16; i++) {
        float4 a = row[i];
        d = fmaf(a.x, zrow[4 * i + 0], d);
        d = fmaf(a.y, zrow[4 * i + 1], d);
        d = fmaf(a.z, zrow[4 * i + 2], d);
        d = fmaf(a.w, zrow[4 * i + 3], d);
    }
    return __fadd_rn(__fsub_rn(zn, __fmul_rn(2.0f, d)), cn);
}

// ---------------------------------------------------------------------------
// Prep: warp per code. cn by xor-shuffle (order-insensitive, R7-proven),
// then lanes 0-15 write the 16 uint2 B-fragment slots of this code.
// Slot for (group g=k>>3, kstep kk, consumer lane n*4+t):
//   b0 = bf16x2(c[16kk+2t], c[16kk+2t+1]), b1 = bf16x2(c[16kk+2t+8], c[..+9])
// ---------------------------------------------------------------------------
__global__ void prep_kernel(const float* __restrict__ cb) {
    int k = (blockIdx.x * blockDim.x + threadIdx.x) >> 5;
    int l = threadIdx.x & 31;
    if (k >= NUM_CODES) return;
    const float* row = cb + (size_t)k * DIM;
    float2 v = *(const float2*)(row + 2 * l);
    float cn = fmaf(v.x, v.x, v.y * v.y);
#pragma unroll
    for (int off = 16; off; off >>= 1)
        cn += __shfl_xor_sync(0xFFFFFFFFu, cn, off);
    if (l == 0) g_cnorm[k] = cn;

    if (l < 16) {
        int kk = l >> 2, t = l & 3;
        int g = k >> 3, n = k & 7;
        int d0 = 16 * kk + 2 * t;
        uint2 val;
        val.x = pk_bf2(row[d0 + 0], row[d0 + 1]);
        val.y = pk_bf2(row[d0 + 8], row[d0 + 9]);
        g_bfrag[(g * 4 + kk) * 32 + n * 4 + t] = val;
    }
}

// ---------------------------------------------------------------------------
// Main
// ---------------------------------------------------------------------------
__global__ void __launch_bounds__(TPB, 1)
vq_main_kernel(const float* __restrict__ z,
               const float* __restrict__ cb,
               float* __restrict__ out,
               float* __restrict__ loss_out) {
    extern __shared__ __align__(16) unsigned char smem[];
    const uint2* s_cb  = (const uint2*)(smem + OFF_CB);
    float*       s_z   = (float*)(smem + OFF_Z);
    float*       s_cn  = (float*)(smem + OFF_CN);
    int*         s_best= (int*)(smem + OFF_BEST);
    float*       s_red = (float*)(smem + OFF_RED);

    const int tid  = threadIdx.x;
    const int w    = tid >> 5, lane = tid & 31;
    const int gid  = lane >> 2, tig = lane & 3;

    // Stage the full fragment codebook (16 uint4 per thread, coalesced).
    {
        const uint4* src = (const uint4*)g_bfrag;
        uint4*       dst = (uint4*)(smem + OFF_CB);
#pragma unroll
        for (int i = 0; i < 16; i++) dst[i * TPB + tid] = src[i * TPB + tid];
    }
    // cn table
    s_cn[tid] = g_cnorm[tid];
    s_cn[tid + TPB] = g_cnorm[tid + TPB];
    // Stage z: two threads per vector, 32 dims each (coalesced across warp).
    {
        int vz = tid >> 1, hf = tid & 1;
        int nz = blockIdx.x * 256 + vz;
        const float* zsrc = z + ((size_t)(nz >> 10) << 16) + (nz & (HW - 1));
#pragma unroll
        for (int i = 0; i < 32; i++) {
            int c = hf * 32 + i;
            s_z[vz * DIM + c] = zsrc[(size_t)c << 10];
        }
    }
    __syncthreads();

    // A fragments: rows rA=w*16+gid, rB=rA+8; values -2z in bf16 (rne).
    const int rA = w * 16 + gid, rB = rA + 8;
    const float* zrA = s_z + rA * DIM;
    const float* zrB = s_z + rB * DIM;
    uint32_t afr[4][4];
#pragma unroll
    for (int kk = 0; kk < 4; kk++) {
        int c0 = 16 * kk + 2 * tig;
        afr[kk][0] = pk_bf2(-2.0f * zrA[c0],     -2.0f * zrA[c0 + 1]);
        afr[kk][1] = pk_bf2(-2.0f * zrB[c0],     -2.0f * zrB[c0 + 1]);
        afr[kk][2] = pk_bf2(-2.0f * zrA[c0 + 8], -2.0f * zrA[c0 + 9]);
        afr[kk][3] = pk_bf2(-2.0f * zrB[c0 + 8], -2.0f * zrB[c0 + 9]);
    }

    // zn in the reference's sequential order (same bits as the R2 passer).
    float znA = 0.0f, znB = 0.0f;
#pragma unroll
    for (int c = 0; c < DIM; c++) znA = fmaf(zrA[c], zrA[c], znA);
#pragma unroll
    for (int c = 0; c < DIM; c++) znB = fmaf(zrB[c], zrB[c], znB);

    // Filter: 2 streams per thread (rows rA/rB, cols {2tig,2tig+1} of each
    // 8-code group). Candidates -> per-pass bitmask, rescored immediately.
    float thA = INF, rmA = INF, thB = INF, rmB = INF;
    float bestA = INF, bestB = INF;
    int   bkA = 0, bkB = 0;

#pragma unroll 1
    for (int p = 0; p < NPASS; p++) {
        uint32_t wbits = 0;
#pragma unroll
        for (int g2 = 0; g2 < GPP; g2++) {
            int g = p * GPP + g2;
            float d[4] = {0.f, 0.f, 0.f, 0.f};
#pragma unroll
            for (int kk = 0; kk < 4; kk++) {
                uint2 bb = s_cb[(g * 4 + kk) * 32 + lane];
                mma_bf16(d, afr[kk], bb.x, bb.y);
            }
            float2 cn2 = *(const float2*)&s_cn[g * 8 + 2 * tig];
            float sA0 = d[0] + cn2.x, sA1 = d[1] + cn2.y;
            float sB0 = d[2] + cn2.x, sB1 = d[3] + cn2.y;
            if (sA0 < thA) { wbits |= 1u << (2 * g2);
                if (sA0 < rmA) { rmA = sA0; thA = rmA + EPS2; } }
            if (sA1 < thA) { wbits |= 1u << (2 * g2 + 1);
                if (sA1 < rmA) { rmA = sA1; thA = rmA + EPS2; } }
            if (sB0 < thB) { wbits |= 0x10000u << (2 * g2);
                if (sB0 < rmB) { rmB = sB0; thB = rmB + EPS2; } }
            if (sB1 < thB) { wbits |= 0x10000u << (2 * g2 + 1);
                if (sB1 < rmB) { rmB = sB1; thB = rmB + EPS2; } }
        }
        // Exact-rescore this pass's candidates (ascending k; strict <).
        uint32_t uA = wbits & 0xFFFFu;
        while (uA) {
            int bit = __ffs(uA) - 1; uA &= uA - 1;
            int k = (p * GPP + (bit >> 1)) * 8 + 2 * tig + (bit & 1);
            float s = exact_score(cb, k, zrA, znA, s_cn[k]);
            if (s < bestA) { bestA = s; bkA = k; }
        }
        uint32_t uB = wbits >> 16;
        while (uB) {
            int bit = __ffs(uB) - 1; uB &= uB - 1;
            int k = (p * GPP + (bit >> 1)) * 8 + 2 * tig + (bit & 1);
            float s = exact_score(cb, k, zrB, znB, s_cn[k]);
            if (s < bestB) { bestB = s; bkB = k; }
        }
        __syncwarp();   // reconverge before the next pass's mma.sync
    }

    // Merge the 4 column-quarters of each row; exact ties -> smaller k.
#pragma unroll
    for (int dlt = 1; dlt < 4; dlt <<= 1) {
        float ob = __shfl_xor_sync(0xFFFFFFFFu, bestA, dlt);
        int   ok = __shfl_xor_sync(0xFFFFFFFFu, bkA, dlt);
        if (ob < bestA || (ob == bestA && ok < bkA)) { bestA = ob; bkA = ok; }
        ob = __shfl_xor_sync(0xFFFFFFFFu, bestB, dlt);
        ok = __shfl_xor_sync(0xFFFFFFFFu, bkB, dlt);
        if (ob < bestB || (ob == bestB && ok < bkB)) { bestB = ob; bkB = ok; }
    }
    if (tig == 0) {
        s_best[rA] = bkA;
        s_best[rB] = bkB;
    }
    __syncwarp();

    // Epilogue: 2 lanes per row write 32 dims each (R2-identical rounding).
    const int r  = lane & 15, hf = lane >> 4;
    const int lr = w * 16 + r;
    const int nv = blockIdx.x * 256 + lr;
    const int bk = s_best[lr];
    const float* crow = cb + (size_t)bk * DIM;
    const float* zrow = s_z + lr * DIM;
    float* op = out + ((size_t)(nv >> 10) << 16) + (nv & (HW - 1));
    float lsum = 0.0f;
#pragma unroll
    for (int i = 0; i < 32; i++) {
        int c = hf * 32 + i;
        float q = crow[c];
        float zv = zrow[c];
        float d = __fsub_rn(q, zv);
        lsum = fmaf(d, d, lsum);
        op[(size_t)c << 10] = __fadd_rn(zv, d);
    }

    // Deterministic block loss reduction.
    __syncthreads();
    s_red[tid] = lsum;
    __syncthreads();
#pragma unroll
    for (int st = TPB / 2; st > 0; st >>= 1) {
        if (tid < st) s_red[tid] += s_red[tid + st];
        __syncthreads();
    }
    if (tid == 0) g_partial[blockIdx.x] = s_red[0];

    // Fused finale: last CTA reduces all partials in fixed order.
    if (loss_out) {
        __shared__ unsigned int s_rank;
        if (tid == 0) {
            __threadfence();
            s_rank = atomicAdd(&g_done, 1u);
        }
        __syncthreads();
        if (s_rank == NBLOCKS - 1) {
            __threadfence();
            s_red[tid] = (tid < NBLOCKS) ? g_partial[tid] : 0.0f;
            __syncthreads();
#pragma unroll
            for (int st = TPB / 2; st > 0; st >>= 1) {
                if (tid < st) s_red[tid] += s_red[tid + st];
                __syncthreads();
            }
            if (tid == 0) {
                loss_out[0] = s_red[0] * (1.25f / (float)N_TOTAL);
                g_done = 0;   // reset for graph replay
            }
        }
    }
}

// ---------------------------------------------------------------------------
extern "C" void kernel_launch(void* const* d_in, const int* in_sizes, int n_in,
                              void* d_out, int out_size) {
    const float* z  = (const float*)d_in[0];
    const float* cb = (const float*)d_in[1];
    float* out = (float*)d_out;
    float* loss_out = (out_size > N_TOTAL) ? (out + (out_size - 1)) : nullptr;

    cudaFuncSetAttribute(vq_main_kernel,
                         cudaFuncAttributeMaxDynamicSharedMemorySize, SMEM_TOTAL);

    prep_kernel<<<NUM_CODES / 8, 256>>>(cb);
    vq_main_kernel<<<NBLOCKS, TPB, SMEM_TOTAL>>>(z, cb, out, loss_out);
}